// round 1
// baseline (speedup 1.0000x reference)
#include <cuda_runtime.h>
#include <cuda_bf16.h>
#include <math.h>

// Problem constants (fixed by the dataset)
#define MAXN 25000
#define MAXE 400000
#define IN_DIM 128
#define H_DIM 4
#define F_DIM 64
#define HF 256          // H*F
#define HIN 512         // H*IN

#define NEG_SLOPE 0.2f

// ---------------- device scratch (no allocations allowed) ----------------
__device__ float g_feat_hf[(size_t)MAXN * HF];   // 25.6 MB
__device__ float g_el[MAXN * H_DIM];
__device__ float g_er[MAXN * H_DIM];
__device__ float g_agg[(size_t)MAXN * HIN];      // 51.2 MB
__device__ int   g_count[MAXN];
__device__ int   g_off[MAXN + 1];
__device__ int   g_cursor[MAXN];
__device__ int   g_eid[MAXE];

__device__ __forceinline__ float lrelu(float x) {
    return x > 0.0f ? x : NEG_SLOPE * x;
}

// ---------------- 1. GEMM: feat_hf = feat @ W^T  ([N,128] x [256,128]^T) ----
__global__ __launch_bounds__(256) void gemm_kernel(
    const float* __restrict__ feat, const float* __restrict__ Wm, int N)
{
    __shared__ float As[64][68];   // [k][row], padded
    __shared__ float Bs[64][68];   // [k][col]
    int t = threadIdx.x;
    int row0 = blockIdx.x * 64;
    int col0 = blockIdx.y * 64;
    int ty = t >> 4, tx = t & 15;
    float acc[4][4] = {};

    for (int kt = 0; kt < 2; kt++) {
#pragma unroll
        for (int i = 0; i < 4; i++) {
            int idx = t + i * 256;     // 0..1023
            int r = idx >> 4;          // 0..63
            int k4 = idx & 15;         // 0..15
            int row = row0 + r;
            float4 v = make_float4(0.f, 0.f, 0.f, 0.f);
            if (row < N) v = *(const float4*)&feat[(size_t)row * IN_DIM + kt * 64 + k4 * 4];
            As[k4 * 4 + 0][r] = v.x; As[k4 * 4 + 1][r] = v.y;
            As[k4 * 4 + 2][r] = v.z; As[k4 * 4 + 3][r] = v.w;
            float4 w = *(const float4*)&Wm[(size_t)(col0 + r) * IN_DIM + kt * 64 + k4 * 4];
            Bs[k4 * 4 + 0][r] = w.x; Bs[k4 * 4 + 1][r] = w.y;
            Bs[k4 * 4 + 2][r] = w.z; Bs[k4 * 4 + 3][r] = w.w;
        }
        __syncthreads();
#pragma unroll 16
        for (int k = 0; k < 64; k++) {
            float4 a = *(const float4*)&As[k][ty * 4];
            float4 b = *(const float4*)&Bs[k][tx * 4];
            acc[0][0] += a.x * b.x; acc[0][1] += a.x * b.y; acc[0][2] += a.x * b.z; acc[0][3] += a.x * b.w;
            acc[1][0] += a.y * b.x; acc[1][1] += a.y * b.y; acc[1][2] += a.y * b.z; acc[1][3] += a.y * b.w;
            acc[2][0] += a.z * b.x; acc[2][1] += a.z * b.y; acc[2][2] += a.z * b.z; acc[2][3] += a.z * b.w;
            acc[3][0] += a.w * b.x; acc[3][1] += a.w * b.y; acc[3][2] += a.w * b.z; acc[3][3] += a.w * b.w;
        }
        __syncthreads();
    }
#pragma unroll
    for (int i = 0; i < 4; i++) {
        int row = row0 + ty * 4 + i;
        if (row < N)
            *(float4*)&g_feat_hf[(size_t)row * HF + col0 + tx * 4] =
                make_float4(acc[i][0], acc[i][1], acc[i][2], acc[i][3]);
    }
}

// ---------------- 2. el / er per (node, head): warp reduce over F=64 ---------
__global__ void elr_kernel(const float* __restrict__ attn_l,
                           const float* __restrict__ attn_r, int N)
{
    int w = (blockIdx.x * blockDim.x + threadIdx.x) >> 5;
    int lane = threadIdx.x & 31;
    if (w >= N * H_DIM) return;
    int n = w >> 2, h = w & 3;
    float2 f  = *(const float2*)&g_feat_hf[(size_t)n * HF + h * F_DIM + lane * 2];
    float2 al = *(const float2*)&attn_l[h * F_DIM + lane * 2];
    float2 ar = *(const float2*)&attn_r[h * F_DIM + lane * 2];
    float sl = f.x * al.x + f.y * al.y;
    float sr = f.x * ar.x + f.y * ar.y;
#pragma unroll
    for (int o = 16; o; o >>= 1) {
        sl += __shfl_xor_sync(0xffffffffu, sl, o);
        sr += __shfl_xor_sync(0xffffffffu, sr, o);
    }
    if (lane == 0) { g_el[n * 4 + h] = sl; g_er[n * 4 + h] = sr; }
}

// ---------------- 3. CSR build by dst ---------------------------------------
__global__ void zero_count_kernel(int N) {
    int i = blockIdx.x * blockDim.x + threadIdx.x;
    if (i < N) g_count[i] = 0;
}
__global__ void hist_kernel(const int* __restrict__ dst, int E) {
    int e = blockIdx.x * blockDim.x + threadIdx.x;
    if (e < E) atomicAdd(&g_count[dst[e]], 1);
}
__global__ void scan_kernel(int N, int E) {
    __shared__ int sums[1024];
    int t = threadIdx.x;
    int chunk = (N + 1023) >> 10;
    int begin = t * chunk;
    int end = min(begin + chunk, N);
    int s = 0;
    for (int i = begin; i < end; i++) s += g_count[i];
    sums[t] = s;
    __syncthreads();
    for (int d = 1; d < 1024; d <<= 1) {
        int v = (t >= d) ? sums[t - d] : 0;
        __syncthreads();
        sums[t] += v;
        __syncthreads();
    }
    int run = (t == 0) ? 0 : sums[t - 1];
    for (int i = begin; i < end; i++) {
        g_off[i] = run; g_cursor[i] = run; run += g_count[i];
    }
    if (t == 1023) g_off[N] = sums[1023];
}
__global__ void scatter_kernel(const int* __restrict__ dst, int E) {
    int e = blockIdx.x * blockDim.x + threadIdx.x;
    if (e < E) {
        int pos = atomicAdd(&g_cursor[dst[e]], 1);
        g_eid[pos] = e;
    }
}

// ---------------- 4. per-dst-node softmax + both aggregations ----------------
// One warp per node. Pass1: lane-parallel edge max. Pass2: lanes cooperate per
// edge (shfl-broadcast cached e/src for deg<=32), accumulate unnormalized sums
// in registers, scale by 1/sum at the end. No float atomics anywhere.
__global__ __launch_bounds__(256) void agg_kernel(
    const float* __restrict__ feat, const int* __restrict__ src,
    float* __restrict__ rst, int N)
{
    int w = (blockIdx.x * blockDim.x + threadIdx.x) >> 5;
    int lane = threadIdx.x & 31;
    if (w >= N) return;
    int n = w;
    int start = g_off[n];
    int deg = g_off[n + 1] - start;

    if (deg == 0) {
#pragma unroll
        for (int h = 0; h < H_DIM; h++) {
            *(float2*)&rst[(size_t)n * HF + h * F_DIM + lane * 2] = make_float2(0.f, 0.f);
            *(float4*)&g_agg[(size_t)n * HIN + h * IN_DIM + lane * 4] = make_float4(0.f, 0.f, 0.f, 0.f);
        }
        return;
    }

    float4 er4 = *(const float4*)&g_er[n * 4];

    // pass 1: per-lane e values for first 32 edges (cached), max reduce
    int mysrc = 0;
    float e0 = -1e30f, e1 = -1e30f, e2 = -1e30f, e3 = -1e30f;
    if (lane < deg) {
        int eid = g_eid[start + lane];
        mysrc = src[eid];
        float4 el4 = *(const float4*)&g_el[mysrc * 4];
        e0 = lrelu(el4.x + er4.x); e1 = lrelu(el4.y + er4.y);
        e2 = lrelu(el4.z + er4.z); e3 = lrelu(el4.w + er4.w);
    }
    float m0 = e0, m1 = e1, m2 = e2, m3 = e3;
    for (int j = 32 + lane; j < deg; j += 32) {
        int eid = g_eid[start + j];
        int s = src[eid];
        float4 el4 = *(const float4*)&g_el[s * 4];
        m0 = fmaxf(m0, lrelu(el4.x + er4.x)); m1 = fmaxf(m1, lrelu(el4.y + er4.y));
        m2 = fmaxf(m2, lrelu(el4.z + er4.z)); m3 = fmaxf(m3, lrelu(el4.w + er4.w));
    }
#pragma unroll
    for (int o = 16; o; o >>= 1) {
        m0 = fmaxf(m0, __shfl_xor_sync(0xffffffffu, m0, o));
        m1 = fmaxf(m1, __shfl_xor_sync(0xffffffffu, m1, o));
        m2 = fmaxf(m2, __shfl_xor_sync(0xffffffffu, m2, o));
        m3 = fmaxf(m3, __shfl_xor_sync(0xffffffffu, m3, o));
    }

    // pass 2: accumulate
    float aR00 = 0.f, aR01 = 0.f, aR10 = 0.f, aR11 = 0.f;
    float aR20 = 0.f, aR21 = 0.f, aR30 = 0.f, aR31 = 0.f;
    float aO[4][4] = {};
    float s0 = 0.f, s1 = 0.f, s2 = 0.f, s3 = 0.f;

    int dmain = min(deg, 32);
    const float2* fhf;
    for (int j = 0; j < dmain; j++) {
        int s = __shfl_sync(0xffffffffu, mysrc, j);
        float ex0 = __expf(__shfl_sync(0xffffffffu, e0, j) - m0);
        float ex1 = __expf(__shfl_sync(0xffffffffu, e1, j) - m1);
        float ex2 = __expf(__shfl_sync(0xffffffffu, e2, j) - m2);
        float ex3 = __expf(__shfl_sync(0xffffffffu, e3, j) - m3);
        s0 += ex0; s1 += ex1; s2 += ex2; s3 += ex3;
        fhf = (const float2*)&g_feat_hf[(size_t)s * HF];
        float2 v0 = fhf[0 * 32 + lane];
        float2 v1 = fhf[1 * 32 + lane];
        float2 v2 = fhf[2 * 32 + lane];
        float2 v3 = fhf[3 * 32 + lane];
        aR00 += ex0 * v0.x; aR01 += ex0 * v0.y;
        aR10 += ex1 * v1.x; aR11 += ex1 * v1.y;
        aR20 += ex2 * v2.x; aR21 += ex2 * v2.y;
        aR30 += ex3 * v3.x; aR31 += ex3 * v3.y;
        float4 fv = *(const float4*)&feat[(size_t)s * IN_DIM + lane * 4];
        aO[0][0] += ex0 * fv.x; aO[0][1] += ex0 * fv.y; aO[0][2] += ex0 * fv.z; aO[0][3] += ex0 * fv.w;
        aO[1][0] += ex1 * fv.x; aO[1][1] += ex1 * fv.y; aO[1][2] += ex1 * fv.z; aO[1][3] += ex1 * fv.w;
        aO[2][0] += ex2 * fv.x; aO[2][1] += ex2 * fv.y; aO[2][2] += ex2 * fv.z; aO[2][3] += ex2 * fv.w;
        aO[3][0] += ex3 * fv.x; aO[3][1] += ex3 * fv.y; aO[3][2] += ex3 * fv.z; aO[3][3] += ex3 * fv.w;
    }
    for (int j = 32; j < deg; j++) {
        int eid = g_eid[start + j];
        int s = src[eid];
        float4 el4 = *(const float4*)&g_el[s * 4];
        float ex0 = __expf(lrelu(el4.x + er4.x) - m0);
        float ex1 = __expf(lrelu(el4.y + er4.y) - m1);
        float ex2 = __expf(lrelu(el4.z + er4.z) - m2);
        float ex3 = __expf(lrelu(el4.w + er4.w) - m3);
        s0 += ex0; s1 += ex1; s2 += ex2; s3 += ex3;
        fhf = (const float2*)&g_feat_hf[(size_t)s * HF];
        float2 v0 = fhf[0 * 32 + lane];
        float2 v1 = fhf[1 * 32 + lane];
        float2 v2 = fhf[2 * 32 + lane];
        float2 v3 = fhf[3 * 32 + lane];
        aR00 += ex0 * v0.x; aR01 += ex0 * v0.y;
        aR10 += ex1 * v1.x; aR11 += ex1 * v1.y;
        aR20 += ex2 * v2.x; aR21 += ex2 * v2.y;
        aR30 += ex3 * v3.x; aR31 += ex3 * v3.y;
        float4 fv = *(const float4*)&feat[(size_t)s * IN_DIM + lane * 4];
        aO[0][0] += ex0 * fv.x; aO[0][1] += ex0 * fv.y; aO[0][2] += ex0 * fv.z; aO[0][3] += ex0 * fv.w;
        aO[1][0] += ex1 * fv.x; aO[1][1] += ex1 * fv.y; aO[1][2] += ex1 * fv.z; aO[1][3] += ex1 * fv.w;
        aO[2][0] += ex2 * fv.x; aO[2][1] += ex2 * fv.y; aO[2][2] += ex2 * fv.z; aO[2][3] += ex2 * fv.w;
        aO[3][0] += ex3 * fv.x; aO[3][1] += ex3 * fv.y; aO[3][2] += ex3 * fv.z; aO[3][3] += ex3 * fv.w;
    }

    float i0 = 1.0f / s0, i1 = 1.0f / s1, i2 = 1.0f / s2, i3 = 1.0f / s3;

    *(float2*)&rst[(size_t)n * HF + 0 * F_DIM + lane * 2] =
        make_float2(fmaxf(aR00 * i0, 0.f), fmaxf(aR01 * i0, 0.f));
    *(float2*)&rst[(size_t)n * HF + 1 * F_DIM + lane * 2] =
        make_float2(fmaxf(aR10 * i1, 0.f), fmaxf(aR11 * i1, 0.f));
    *(float2*)&rst[(size_t)n * HF + 2 * F_DIM + lane * 2] =
        make_float2(fmaxf(aR20 * i2, 0.f), fmaxf(aR21 * i2, 0.f));
    *(float2*)&rst[(size_t)n * HF + 3 * F_DIM + lane * 2] =
        make_float2(fmaxf(aR30 * i3, 0.f), fmaxf(aR31 * i3, 0.f));

    float inv[4] = { i0, i1, i2, i3 };
#pragma unroll
    for (int h = 0; h < 4; h++) {
        *(float4*)&g_agg[(size_t)n * HIN + h * IN_DIM + lane * 4] =
            make_float4(aO[h][0] * inv[h], aO[h][1] * inv[h], aO[h][2] * inv[h], aO[h][3] * inv[h]);
    }
}

// ---------------- 5. out_edge = |agg[src] - agg[dst]| per edge ---------------
// Iterated in CSR (dst-grouped) order so consecutive warps hit the same dst
// row in L1; src rows come from L2. Writes go to out[eid].
__global__ __launch_bounds__(256) void edge_out_kernel(
    const int* __restrict__ src, const int* __restrict__ dst,
    float* __restrict__ out, int E)
{
    int p = (blockIdx.x * blockDim.x + threadIdx.x) >> 5;
    int lane = threadIdx.x & 31;
    if (p >= E) return;
    int eid = g_eid[p];
    int s = src[eid];
    int d = dst[eid];
    const float4* as = (const float4*)&g_agg[(size_t)s * HIN];
    const float4* ad = (const float4*)&g_agg[(size_t)d * HIN];
    float4* o = (float4*)&out[(size_t)eid * HIN];
#pragma unroll
    for (int h = 0; h < 4; h++) {
        float4 a = as[h * 32 + lane];
        float4 b = ad[h * 32 + lane];
        o[h * 32 + lane] = make_float4(fabsf(a.x - b.x), fabsf(a.y - b.y),
                                       fabsf(a.z - b.z), fabsf(a.w - b.w));
    }
}

// ---------------- launch -----------------------------------------------------
extern "C" void kernel_launch(void* const* d_in, const int* in_sizes, int n_in,
                              void* d_out, int out_size)
{
    const float* feat   = (const float*)d_in[0];
    const float* Wm     = (const float*)d_in[1];
    const float* attn_l = (const float*)d_in[2];
    const float* attn_r = (const float*)d_in[3];
    const int*   src    = (const int*)d_in[4];
    const int*   dst    = (const int*)d_in[5];
    int N = in_sizes[0] / IN_DIM;
    int E = in_sizes[4];
    float* out = (float*)d_out;

    // 1. fc GEMM
    gemm_kernel<<<dim3((N + 63) / 64, 4), 256>>>(feat, Wm, N);
    // 2. attention logits per node
    elr_kernel<<<(N * H_DIM * 32 + 255) / 256, 256>>>(attn_l, attn_r, N);
    // 3. CSR by dst
    zero_count_kernel<<<(N + 255) / 256, 256>>>(N);
    hist_kernel<<<(E + 255) / 256, 256>>>(dst, E);
    scan_kernel<<<1, 1024>>>(N, E);
    scatter_kernel<<<(E + 255) / 256, 256>>>(dst, E);
    // 4. softmax + aggregation (writes rst into d_out[0 : N*256))
    agg_kernel<<<(N * 32 + 255) / 256, 256>>>(feat, src, out, N);
    // 5. edge output (writes d_out[N*256 : N*256 + E*512))
    edge_out_kernel<<<((size_t)E * 32 + 255) / 256, 256>>>(
        src, dst, out + (size_t)N * HF, E);
}

// round 3
// speedup vs baseline: 1.1073x; 1.1073x over previous
#include <cuda_runtime.h>
#include <cuda_bf16.h>
#include <math.h>

// Problem constants (fixed by the dataset)
#define MAXN 25000
#define MAXE 400000
#define IN_DIM 128
#define H_DIM 4
#define F_DIM 64
#define HF 256          // H*F
#define HIN 512         // H*IN

#define NEG_SLOPE 0.2f

// ---------------- device scratch (no allocations allowed) ----------------
__device__ __align__(16) float g_wl[H_DIM * IN_DIM];   // folded attn_l @ W
__device__ __align__(16) float g_wr[H_DIM * IN_DIM];   // folded attn_r @ W
__device__ __align__(16) float g_el[MAXN * H_DIM];
__device__ __align__(16) float g_er[MAXN * H_DIM];
__device__ __align__(16) float g_agg[(size_t)MAXN * HIN];   // 51.2 MB
__device__ int   g_count[MAXN];
__device__ int   g_off[MAXN + 1];
__device__ int   g_cursor[MAXN];
__device__ int   g_eid[MAXE];

__device__ __forceinline__ float lrelu(float x) {
    return x > 0.0f ? x : NEG_SLOPE * x;
}

// ---------------- 0. fold attention vectors into W ------------------------
// wl[h][i] = sum_f attn_l[h,f] * W[h*F+f, i]   (W is [H*F, IN] row-major)
__global__ void prep_kernel(const float* __restrict__ Wm,
                            const float* __restrict__ attn_l,
                            const float* __restrict__ attn_r)
{
    int t = blockIdx.x * blockDim.x + threadIdx.x;   // 0..511
    if (t >= H_DIM * IN_DIM) return;
    int h = t >> 7, i = t & 127;
    float sl = 0.f, sr = 0.f;
    const float* wbase = Wm + (size_t)h * F_DIM * IN_DIM + i;
#pragma unroll 8
    for (int f = 0; f < F_DIM; f++) {
        float w = wbase[(size_t)f * IN_DIM];
        sl += attn_l[h * F_DIM + f] * w;
        sr += attn_r[h * F_DIM + f] * w;
    }
    g_wl[t] = sl;
    g_wr[t] = sr;
}

// ---------------- 1. el / er per node: warp per node ------------------------
__global__ void elr_kernel(const float* __restrict__ feat, int N)
{
    int w = (blockIdx.x * blockDim.x + threadIdx.x) >> 5;
    int lane = threadIdx.x & 31;
    if (w >= N) return;
    float4 fv = *(const float4*)&feat[(size_t)w * IN_DIM + lane * 4];
    float sl[4], sr[4];
#pragma unroll
    for (int h = 0; h < 4; h++) {
        float4 a = *(const float4*)&g_wl[h * IN_DIM + lane * 4];
        float4 b = *(const float4*)&g_wr[h * IN_DIM + lane * 4];
        sl[h] = fv.x * a.x + fv.y * a.y + fv.z * a.z + fv.w * a.w;
        sr[h] = fv.x * b.x + fv.y * b.y + fv.z * b.z + fv.w * b.w;
    }
#pragma unroll
    for (int o = 16; o; o >>= 1) {
#pragma unroll
        for (int h = 0; h < 4; h++) {
            sl[h] += __shfl_xor_sync(0xffffffffu, sl[h], o);
            sr[h] += __shfl_xor_sync(0xffffffffu, sr[h], o);
        }
    }
    if (lane == 0) {
        *(float4*)&g_el[w * 4] = make_float4(sl[0], sl[1], sl[2], sl[3]);
        *(float4*)&g_er[w * 4] = make_float4(sr[0], sr[1], sr[2], sr[3]);
    }
}

// ---------------- 2. CSR build by dst ---------------------------------------
__global__ void zero_count_kernel(int N) {
    int i = blockIdx.x * blockDim.x + threadIdx.x;
    if (i < N) g_count[i] = 0;
}
__global__ void hist_kernel(const int* __restrict__ dst, int E) {
    int e = blockIdx.x * blockDim.x + threadIdx.x;
    if (e < E) atomicAdd(&g_count[dst[e]], 1);
}
__global__ void scan_kernel(int N, int E) {
    __shared__ int sums[1024];
    int t = threadIdx.x;
    int chunk = (N + 1023) >> 10;
    int begin = t * chunk;
    int end = min(begin + chunk, N);
    int s = 0;
    for (int i = begin; i < end; i++) s += g_count[i];
    sums[t] = s;
    __syncthreads();
    for (int d = 1; d < 1024; d <<= 1) {
        int v = (t >= d) ? sums[t - d] : 0;
        __syncthreads();
        sums[t] += v;
        __syncthreads();
    }
    int run = (t == 0) ? 0 : sums[t - 1];
    for (int i = begin; i < end; i++) {
        g_off[i] = run; g_cursor[i] = run; run += g_count[i];
    }
    if (t == 1023) g_off[N] = sums[1023];
}
__global__ void scatter_kernel(const int* __restrict__ dst, int E) {
    int e = blockIdx.x * blockDim.x + threadIdx.x;
    if (e < E) {
        int pos = atomicAdd(&g_cursor[dst[e]], 1);
        g_eid[pos] = e;
    }
}

// ---------------- 3. per-dst-node softmax + agg_ori aggregation --------------
__global__ __launch_bounds__(256) void agg_kernel(
    const float* __restrict__ feat, const int* __restrict__ src, int N)
{
    int w = (blockIdx.x * blockDim.x + threadIdx.x) >> 5;
    int lane = threadIdx.x & 31;
    if (w >= N) return;
    int n = w;
    int start = g_off[n];
    int deg = g_off[n + 1] - start;

    if (deg == 0) {
#pragma unroll
        for (int h = 0; h < H_DIM; h++)
            *(float4*)&g_agg[(size_t)n * HIN + h * IN_DIM + lane * 4] =
                make_float4(0.f, 0.f, 0.f, 0.f);
        return;
    }

    float4 er4 = *(const float4*)&g_er[n * 4];

    // pass 1: per-lane e values for first 32 edges (cached), max reduce
    int mysrc = 0;
    float e0 = -1e30f, e1 = -1e30f, e2 = -1e30f, e3 = -1e30f;
    if (lane < deg) {
        int eid = g_eid[start + lane];
        mysrc = src[eid];
        float4 el4 = *(const float4*)&g_el[mysrc * 4];
        e0 = lrelu(el4.x + er4.x); e1 = lrelu(el4.y + er4.y);
        e2 = lrelu(el4.z + er4.z); e3 = lrelu(el4.w + er4.w);
    }
    float m0 = e0, m1 = e1, m2 = e2, m3 = e3;
    for (int j = 32 + lane; j < deg; j += 32) {
        int eid = g_eid[start + j];
        int s = src[eid];
        float4 el4 = *(const float4*)&g_el[s * 4];
        m0 = fmaxf(m0, lrelu(el4.x + er4.x)); m1 = fmaxf(m1, lrelu(el4.y + er4.y));
        m2 = fmaxf(m2, lrelu(el4.z + er4.z)); m3 = fmaxf(m3, lrelu(el4.w + er4.w));
    }
#pragma unroll
    for (int o = 16; o; o >>= 1) {
        m0 = fmaxf(m0, __shfl_xor_sync(0xffffffffu, m0, o));
        m1 = fmaxf(m1, __shfl_xor_sync(0xffffffffu, m1, o));
        m2 = fmaxf(m2, __shfl_xor_sync(0xffffffffu, m2, o));
        m3 = fmaxf(m3, __shfl_xor_sync(0xffffffffu, m3, o));
    }

    // pass 2: accumulate unnormalized agg_ori
    float aO[4][4] = {};
    float s0 = 0.f, s1 = 0.f, s2 = 0.f, s3 = 0.f;

    int dmain = min(deg, 32);
    for (int j = 0; j < dmain; j++) {
        int s = __shfl_sync(0xffffffffu, mysrc, j);
        float ex0 = __expf(__shfl_sync(0xffffffffu, e0, j) - m0);
        float ex1 = __expf(__shfl_sync(0xffffffffu, e1, j) - m1);
        float ex2 = __expf(__shfl_sync(0xffffffffu, e2, j) - m2);
        float ex3 = __expf(__shfl_sync(0xffffffffu, e3, j) - m3);
        s0 += ex0; s1 += ex1; s2 += ex2; s3 += ex3;
        float4 fv = *(const float4*)&feat[(size_t)s * IN_DIM + lane * 4];
        aO[0][0] += ex0 * fv.x; aO[0][1] += ex0 * fv.y; aO[0][2] += ex0 * fv.z; aO[0][3] += ex0 * fv.w;
        aO[1][0] += ex1 * fv.x; aO[1][1] += ex1 * fv.y; aO[1][2] += ex1 * fv.z; aO[1][3] += ex1 * fv.w;
        aO[2][0] += ex2 * fv.x; aO[2][1] += ex2 * fv.y; aO[2][2] += ex2 * fv.z; aO[2][3] += ex2 * fv.w;
        aO[3][0] += ex3 * fv.x; aO[3][1] += ex3 * fv.y; aO[3][2] += ex3 * fv.z; aO[3][3] += ex3 * fv.w;
    }
    for (int j = 32; j < deg; j++) {
        int eid = g_eid[start + j];
        int s = src[eid];
        float4 el4 = *(const float4*)&g_el[s * 4];
        float ex0 = __expf(lrelu(el4.x + er4.x) - m0);
        float ex1 = __expf(lrelu(el4.y + er4.y) - m1);
        float ex2 = __expf(lrelu(el4.z + er4.z) - m2);
        float ex3 = __expf(lrelu(el4.w + er4.w) - m3);
        s0 += ex0; s1 += ex1; s2 += ex2; s3 += ex3;
        float4 fv = *(const float4*)&feat[(size_t)s * IN_DIM + lane * 4];
        aO[0][0] += ex0 * fv.x; aO[0][1] += ex0 * fv.y; aO[0][2] += ex0 * fv.z; aO[0][3] += ex0 * fv.w;
        aO[1][0] += ex1 * fv.x; aO[1][1] += ex1 * fv.y; aO[1][2] += ex1 * fv.z; aO[1][3] += ex1 * fv.w;
        aO[2][0] += ex2 * fv.x; aO[2][1] += ex2 * fv.y; aO[2][2] += ex2 * fv.z; aO[2][3] += ex2 * fv.w;
        aO[3][0] += ex3 * fv.x; aO[3][1] += ex3 * fv.y; aO[3][2] += ex3 * fv.z; aO[3][3] += ex3 * fv.w;
    }

    float inv[4] = { 1.0f / s0, 1.0f / s1, 1.0f / s2, 1.0f / s3 };
#pragma unroll
    for (int h = 0; h < 4; h++) {
        *(float4*)&g_agg[(size_t)n * HIN + h * IN_DIM + lane * 4] =
            make_float4(aO[h][0] * inv[h], aO[h][1] * inv[h],
                        aO[h][2] * inv[h], aO[h][3] * inv[h]);
    }
}

// ---------------- 4. rst = relu(agg_ori @ W_h^T) per head --------------------
// Head-batched GEMM: [N,128] @ [128,64]^T per head. Tile 64 nodes x 64 F,
// K in two 64-halves. Smem layout [k][elem] with 68-float pad (272 B, 16B mult).
__global__ __launch_bounds__(256) void rst_gemm_kernel(
    const float* __restrict__ Wm, float* __restrict__ rst, int N)
{
    __shared__ float As[64][68];   // [k][node]
    __shared__ float Bs[64][68];   // [k][f]
    int t = threadIdx.x;
    int row0 = blockIdx.x * 64;
    int h = blockIdx.y;
    int ty = t >> 4, tx = t & 15;
    float acc[4][4] = {};

    const float* Arow = g_agg + (size_t)h * IN_DIM;          // + n*HIN
    const float* Brow = Wm + (size_t)h * F_DIM * IN_DIM;     // + f*IN_DIM

    for (int kt = 0; kt < 2; kt++) {
#pragma unroll
        for (int i = 0; i < 4; i++) {
            int idx = t + i * 256;     // 0..1023
            int r = idx >> 4;          // 0..63
            int k4 = idx & 15;         // 0..15
            int row = row0 + r;
            float4 v = make_float4(0.f, 0.f, 0.f, 0.f);
            if (row < N) v = *(const float4*)&Arow[(size_t)row * HIN + kt * 64 + k4 * 4];
            As[k4 * 4 + 0][r] = v.x; As[k4 * 4 + 1][r] = v.y;
            As[k4 * 4 + 2][r] = v.z; As[k4 * 4 + 3][r] = v.w;
            float4 wv = *(const float4*)&Brow[(size_t)r * IN_DIM + kt * 64 + k4 * 4];
            Bs[k4 * 4 + 0][r] = wv.x; Bs[k4 * 4 + 1][r] = wv.y;
            Bs[k4 * 4 + 2][r] = wv.z; Bs[k4 * 4 + 3][r] = wv.w;
        }
        __syncthreads();
#pragma unroll 16
        for (int k = 0; k < 64; k++) {
            float4 a = *(const float4*)&As[k][ty * 4];
            float4 b = *(const float4*)&Bs[k][tx * 4];
            acc[0][0] += a.x * b.x; acc[0][1] += a.x * b.y; acc[0][2] += a.x * b.z; acc[0][3] += a.x * b.w;
            acc[1][0] += a.y * b.x; acc[1][1] += a.y * b.y; acc[1][2] += a.y * b.z; acc[1][3] += a.y * b.w;
            acc[2][0] += a.z * b.x; acc[2][1] += a.z * b.y; acc[2][2] += a.z * b.z; acc[2][3] += a.z * b.w;
            acc[3][0] += a.w * b.x; acc[3][1] += a.w * b.y; acc[3][2] += a.w * b.z; acc[3][3] += a.w * b.w;
        }
        __syncthreads();
    }
#pragma unroll
    for (int i = 0; i < 4; i++) {
        int row = row0 + ty * 4 + i;
        if (row < N)
            *(float4*)&rst[(size_t)row * HF + h * F_DIM + tx * 4] =
                make_float4(fmaxf(acc[i][0], 0.f), fmaxf(acc[i][1], 0.f),
                            fmaxf(acc[i][2], 0.f), fmaxf(acc[i][3], 0.f));
    }
}

// ---------------- 5. out_edge = |agg[src] - agg[dst]| per edge ---------------
// One warp per dst node: dst row cached in registers (16 floats/lane), then
// stream src rows from L2 and write output.
__global__ __launch_bounds__(256) void edge_out_kernel(
    const int* __restrict__ src, float* __restrict__ out, int N)
{
    int w = (blockIdx.x * blockDim.x + threadIdx.x) >> 5;
    int lane = threadIdx.x & 31;
    if (w >= N) return;
    int start = g_off[w];
    int end = g_off[w + 1];
    if (start == end) return;

    const float4* ad = (const float4*)&g_agg[(size_t)w * HIN];
    float4 bd[4];
#pragma unroll
    for (int h = 0; h < 4; h++) bd[h] = ad[h * 32 + lane];

    int eid = g_eid[start];
    int s = src[eid];
    for (int p = start; p < end; p++) {
        int neid = 0, ns = 0;
        if (p + 1 < end) { neid = g_eid[p + 1]; ns = src[neid]; }
        const float4* as = (const float4*)&g_agg[(size_t)s * HIN];
        float4* o = (float4*)&out[(size_t)eid * HIN];
#pragma unroll
        for (int h = 0; h < 4; h++) {
            float4 a = as[h * 32 + lane];
            o[h * 32 + lane] = make_float4(fabsf(a.x - bd[h].x), fabsf(a.y - bd[h].y),
                                           fabsf(a.z - bd[h].z), fabsf(a.w - bd[h].w));
        }
        eid = neid; s = ns;
    }
}

// ---------------- launch -----------------------------------------------------
extern "C" void kernel_launch(void* const* d_in, const int* in_sizes, int n_in,
                              void* d_out, int out_size)
{
    const float* feat   = (const float*)d_in[0];
    const float* Wm     = (const float*)d_in[1];
    const float* attn_l = (const float*)d_in[2];
    const float* attn_r = (const float*)d_in[3];
    const int*   src    = (const int*)d_in[4];
    const int*   dst    = (const int*)d_in[5];
    int N = in_sizes[0] / IN_DIM;
    int E = in_sizes[4];
    float* out = (float*)d_out;

    // 0. fold attn into W
    prep_kernel<<<2, 256>>>(Wm, attn_l, attn_r);
    // 1. attention logits per node (el, er)
    elr_kernel<<<(N * 32 + 255) / 256, 256>>>(feat, N);
    // 2. CSR by dst
    zero_count_kernel<<<(N + 255) / 256, 256>>>(N);
    hist_kernel<<<(E + 255) / 256, 256>>>(dst, E);
    scan_kernel<<<1, 1024>>>(N, E);
    scatter_kernel<<<(E + 255) / 256, 256>>>(dst, E);
    // 3. softmax + agg_ori aggregation (normalized, into g_agg)
    agg_kernel<<<(N * 32 + 255) / 256, 256>>>(feat, src, N);
    // 4. rst = relu(agg_ori @ W_h^T)  (writes d_out[0 : N*256))
    rst_gemm_kernel<<<dim3((N + 63) / 64, H_DIM), 256>>>(Wm, out, N);
    // 5. edge output (writes d_out[N*256 : N*256 + E*512))
    edge_out_kernel<<<(N * 32 + 255) / 256, 256>>>(src, out + (size_t)N * HF, N);
}